// round 6
// baseline (speedup 1.0000x reference)
#include <cuda_runtime.h>

#define EMBED  1024
#define NHEAD  16
#define HDIM   64
#define BATCH  2
#define QLEN   2048
#define CLEN   2048
#define ROWS   (BATCH * QLEN)   // 4096

// ---------------- scratch (device globals: allocation-free) ----------------
__device__ float g_Q[(size_t)ROWS * EMBED];
__device__ float g_K[(size_t)ROWS * EMBED];
__device__ float g_V[(size_t)ROWS * EMBED];
__device__ float g_A[(size_t)ROWS * EMBED];

// ---------------- packed f32x2 helpers -------------------------------------
typedef unsigned long long u64;

__device__ __forceinline__ u64 pack2(float x, float y) {
    u64 r; asm("mov.b64 %0, {%1, %2};" : "=l"(r) : "f"(x), "f"(y)); return r;
}
__device__ __forceinline__ void fma2(u64& d, u64 a, u64 b) {
    asm("fma.rn.f32x2 %0, %1, %2, %0;" : "+l"(d) : "l"(a), "l"(b));
}
__device__ __forceinline__ void mul2(u64& d, u64 a) {
    asm("mul.rn.f32x2 %0, %0, %1;" : "+l"(d) : "l"(a));
}
__device__ __forceinline__ float2 unp2(u64 v) {
    float2 r; asm("mov.b64 {%0, %1}, %2;" : "=f"(r.x), "=f"(r.y) : "l"(v)); return r;
}

// ---------------- SGEMM 128x128x16 with FFMA2 (j-paired accumulators) ------
__global__ void __launch_bounds__(256, 2)
sgemm_bias(const float* __restrict__ A, const float* __restrict__ W,
           const float* __restrict__ bias, float* __restrict__ C)
{
    const int N = 1024, K = 1024;
    __shared__ float As[16][128];   // [k][m]
    __shared__ float Ws[16][128];   // [k][n]

    const int tid = threadIdx.x;
    const int bm  = blockIdx.y * 128;
    const int bn  = blockIdx.x * 128;
    const int tr  = tid >> 4;
    const int tc  = tid & 15;

    const int a_row = tid >> 2;
    const int a_k4  = (tid & 3) * 4;
    const int w_k   = tid >> 5;
    const int w_c   = (tid & 31) * 4;

    // acc viewed as packed pairs over j: acc2[i][jp] = (c[2jp], c[2jp+1])
    u64 acc2[8][4];
    #pragma unroll
    for (int i = 0; i < 8; i++)
        #pragma unroll
        for (int j = 0; j < 4; j++) acc2[i][j] = 0ULL;

    for (int kt = 0; kt < K; kt += 16) {
        #pragma unroll
        for (int half = 0; half < 2; half++) {
            int row = a_row + half * 64;
            float4 v = *(const float4*)&A[(size_t)(bm + row) * K + kt + a_k4];
            As[a_k4 + 0][row] = v.x;
            As[a_k4 + 1][row] = v.y;
            As[a_k4 + 2][row] = v.z;
            As[a_k4 + 3][row] = v.w;
        }
        #pragma unroll
        for (int half = 0; half < 2; half++) {
            int k = w_k + half * 8;
            float4 v = *(const float4*)&W[(size_t)(kt + k) * N + bn + w_c];
            *(float4*)&Ws[k][w_c] = v;
        }
        __syncthreads();

        #pragma unroll
        for (int k = 0; k < 16; k++) {
            float4 a0 = *(const float4*)&As[k][tr * 8];
            float4 a1 = *(const float4*)&As[k][tr * 8 + 4];
            const ulonglong2* bp = (const ulonglong2*)&Ws[k][tc * 8];
            ulonglong2 bA = bp[0], bB = bp[1];
            u64 b2[4] = {bA.x, bA.y, bB.x, bB.y};
            float av[8] = {a0.x, a0.y, a0.z, a0.w, a1.x, a1.y, a1.z, a1.w};
            #pragma unroll
            for (int i = 0; i < 8; i++) {
                u64 ad = pack2(av[i], av[i]);
                fma2(acc2[i][0], ad, b2[0]);
                fma2(acc2[i][1], ad, b2[1]);
                fma2(acc2[i][2], ad, b2[2]);
                fma2(acc2[i][3], ad, b2[3]);
            }
        }
        __syncthreads();
    }

    float bsv[8];
    #pragma unroll
    for (int j = 0; j < 8; j++) bsv[j] = __ldg(&bias[bn + tc * 8 + j]);
    #pragma unroll
    for (int i = 0; i < 8; i++) {
        float2 p0 = unp2(acc2[i][0]);
        float2 p1 = unp2(acc2[i][1]);
        float2 p2 = unp2(acc2[i][2]);
        float2 p3 = unp2(acc2[i][3]);
        size_t off = (size_t)(bm + tr * 8 + i) * N + bn + tc * 8;
        float4 r0 = make_float4(p0.x + bsv[0], p0.y + bsv[1],
                                p1.x + bsv[2], p1.y + bsv[3]);
        float4 r1 = make_float4(p2.x + bsv[4], p2.y + bsv[5],
                                p3.x + bsv[6], p3.y + bsv[7]);
        *(float4*)&C[off]     = r0;
        *(float4*)&C[off + 4] = r1;
    }
}

// ---------------- flash attention, FFMA2 packed ----------------------------
// BQ=64, BKV=64, 256 threads, occ 2. grid (QLEN/64, B*H) = (32, 32)
#define BQ  64
#define BKV 64
#define QS  68      // float stride (16B aligned rows, conflict-spread)
#define KS  68
#define PS  68
#define VS2 132     // float stride of interleaved V pair-rows (66 float2)
#define FLASH_SMEM_FLOATS (BQ*QS + BKV*KS + BQ*PS + (BKV/2)*VS2)

__global__ void __launch_bounds__(256, 2)
flash_attn(const float* __restrict__ Q, const float* __restrict__ K,
           const float* __restrict__ V, float* __restrict__ O)
{
    extern __shared__ float sm[];
    float* Qs  = sm;
    float* Ks  = Qs + BQ * QS;
    float* Ps  = Ks + BKV * KS;
    float* Vsf = Ps + BQ * PS;   // interleaved: Vsf[kp*VS2 + col*2 + (k&1)]

    const int tid = threadIdx.x;
    const int bh  = blockIdx.y;
    const int b   = bh >> 4;
    const int h   = bh & 15;
    const int q0  = blockIdx.x * BQ;
    const int tr  = tid >> 4;    // 0..15, q rows = tr + i*16
    const int tc  = tid & 15;    // S cols = tc + j*16 ; PV cols = tc*4..+3

    const float scale = 0.125f;  // 1/sqrt(64)

    const float* Qg = Q + ((size_t)(b * QLEN + q0)) * EMBED + h * HDIM;
    const float* Kg = K + ((size_t)b * CLEN) * EMBED + h * HDIM;
    const float* Vg = V + ((size_t)b * CLEN) * EMBED + h * HDIM;

    // load Q tile (pre-scaled): 64x64 floats = 1024 float4, 4 per thread
    #pragma unroll
    for (int it = 0; it < 4; it++) {
        int f = tid + it * 256;
        int row = f >> 4;
        int c4  = (f & 15) * 4;
        float4 v = *(const float4*)&Qg[(size_t)row * EMBED + c4];
        float* q = &Qs[row * QS + c4];
        q[0] = v.x * scale; q[1] = v.y * scale; q[2] = v.z * scale; q[3] = v.w * scale;
    }

    float m[4], l[4];
    u64 o2[4][4];               // packed partial O over (k even, k odd)
    #pragma unroll
    for (int i = 0; i < 4; i++) {
        m[i] = -1e30f; l[i] = 0.f;
        o2[i][0] = o2[i][1] = o2[i][2] = o2[i][3] = 0ULL;
    }

    for (int kt = 0; kt < CLEN; kt += BKV) {
        // load K tile + V tile (V interleaved by k-parity)
        #pragma unroll
        for (int it = 0; it < 4; it++) {
            int f = tid + it * 256;
            int row = f >> 4;
            int c4  = (f & 15) * 4;
            float4 kv = *(const float4*)&Kg[(size_t)(kt + row) * EMBED + c4];
            float* kd = &Ks[row * KS + c4];
            kd[0] = kv.x; kd[1] = kv.y; kd[2] = kv.z; kd[3] = kv.w;
            float4 vv = *(const float4*)&Vg[(size_t)(kt + row) * EMBED + c4];
            float* vd = &Vsf[(row >> 1) * VS2 + (row & 1)];
            vd[(c4 + 0) * 2] = vv.x;
            vd[(c4 + 1) * 2] = vv.y;
            vd[(c4 + 2) * 2] = vv.z;
            vd[(c4 + 3) * 2] = vv.w;
        }
        __syncthreads();

        // --- S = Q K^T : packed partial sums over d (even/odd interleave) ---
        u64 sp[4][4];
        #pragma unroll
        for (int i = 0; i < 4; i++)
            #pragma unroll
            for (int j = 0; j < 4; j++) sp[i][j] = 0ULL;

        #pragma unroll
        for (int d0 = 0; d0 < HDIM; d0 += 4) {
            u64 a01[4], a23[4], b01[4], b23[4];
            #pragma unroll
            for (int i = 0; i < 4; i++) {
                ulonglong2 av = *(const ulonglong2*)&Qs[(tr + i * 16) * QS + d0];
                a01[i] = av.x; a23[i] = av.y;
            }
            #pragma unroll
            for (int j = 0; j < 4; j++) {
                ulonglong2 bv = *(const ulonglong2*)&Ks[(tc + j * 16) * KS + d0];
                b01[j] = bv.x; b23[j] = bv.y;
            }
            #pragma unroll
            for (int i = 0; i < 4; i++)
                #pragma unroll
                for (int j = 0; j < 4; j++) {
                    fma2(sp[i][j], a01[i], b01[j]);
                    fma2(sp[i][j], a23[i], b23[j]);
                }
        }

        // --- online softmax ---
        #pragma unroll
        for (int i = 0; i < 4; i++) {
            float s[4];
            #pragma unroll
            for (int j = 0; j < 4; j++) {
                float2 p = unp2(sp[i][j]);
                s[j] = p.x + p.y;
            }
            float rm = fmaxf(fmaxf(s[0], s[1]), fmaxf(s[2], s[3]));
            rm = fmaxf(rm, __shfl_xor_sync(0xffffffffu, rm, 8));
            rm = fmaxf(rm, __shfl_xor_sync(0xffffffffu, rm, 4));
            rm = fmaxf(rm, __shfl_xor_sync(0xffffffffu, rm, 2));
            rm = fmaxf(rm, __shfl_xor_sync(0xffffffffu, rm, 1));
            float mn = fmaxf(m[i], rm);
            float alpha = __expf(m[i] - mn);
            m[i] = mn;
            float rs = 0.f;
            #pragma unroll
            for (int j = 0; j < 4; j++) {
                s[j] = __expf(s[j] - mn);
                rs += s[j];
            }
            rs += __shfl_xor_sync(0xffffffffu, rs, 8);
            rs += __shfl_xor_sync(0xffffffffu, rs, 4);
            rs += __shfl_xor_sync(0xffffffffu, rs, 2);
            rs += __shfl_xor_sync(0xffffffffu, rs, 1);
            l[i] = l[i] * alpha + rs;
            u64 ad = pack2(alpha, alpha);
            mul2(o2[i][0], ad); mul2(o2[i][1], ad);
            mul2(o2[i][2], ad); mul2(o2[i][3], ad);
            // stage P (scattered scalar stores, consecutive-tc -> conflict-free)
            float* pr = &Ps[(tr + i * 16) * PS + tc];
            pr[0]  = s[0];
            pr[16] = s[1];
            pr[32] = s[2];
            pr[48] = s[3];
        }
        __syncthreads();

        // --- O += P @ V : packed over k-pairs ---
        #pragma unroll 4
        for (int kp = 0; kp < BKV / 2; kp++) {
            const ulonglong2* vp = (const ulonglong2*)&Vsf[kp * VS2 + tc * 8];
            ulonglong2 vA = vp[0], vB = vp[1];
            u64 v2[4] = {vA.x, vA.y, vB.x, vB.y};
            #pragma unroll
            for (int i = 0; i < 4; i++) {
                u64 p2 = *(const u64*)&Ps[(tr + i * 16) * PS + 2 * kp];
                fma2(o2[i][0], p2, v2[0]);
                fma2(o2[i][1], p2, v2[1]);
                fma2(o2[i][2], p2, v2[2]);
                fma2(o2[i][3], p2, v2[3]);
            }
        }
        __syncthreads();
    }

    // epilogue: collapse pairs, normalize, write
    float* Og = O + ((size_t)(b * QLEN + q0)) * EMBED + h * HDIM;
    #pragma unroll
    for (int i = 0; i < 4; i++) {
        float inv = 1.f / l[i];
        float2 c0 = unp2(o2[i][0]);
        float2 c1 = unp2(o2[i][1]);
        float2 c2 = unp2(o2[i][2]);
        float2 c3 = unp2(o2[i][3]);
        float4 r = make_float4((c0.x + c0.y) * inv, (c1.x + c1.y) * inv,
                               (c2.x + c2.y) * inv, (c3.x + c3.y) * inv);
        *(float4*)&Og[(size_t)(tr + i * 16) * EMBED + tc * 4] = r;
    }
}

// ---------------- launcher --------------------------------------------------
extern "C" void kernel_launch(void* const* d_in, const int* in_sizes, int n_in,
                              void* d_out, int out_size)
{
    (void)in_sizes; (void)n_in; (void)out_size;
    const float* query   = (const float*)d_in[0];
    const float* context = (const float*)d_in[1];
    const float* Wq = (const float*)d_in[2];
    const float* bq = (const float*)d_in[3];
    const float* Wk = (const float*)d_in[4];
    const float* bk = (const float*)d_in[5];
    const float* Wv = (const float*)d_in[6];
    const float* bv = (const float*)d_in[7];
    const float* Wo = (const float*)d_in[8];
    const float* bo = (const float*)d_in[9];

    float *Qb, *Kb, *Vb, *Ab;
    cudaGetSymbolAddress((void**)&Qb, g_Q);
    cudaGetSymbolAddress((void**)&Kb, g_K);
    cudaGetSymbolAddress((void**)&Vb, g_V);
    cudaGetSymbolAddress((void**)&Ab, g_A);

    dim3 gemm_grid(EMBED / 128, ROWS / 128);   // (8, 32)
    sgemm_bias<<<gemm_grid, 256>>>(query,   Wq, bq, Qb);
    sgemm_bias<<<gemm_grid, 256>>>(context, Wk, bk, Kb);
    sgemm_bias<<<gemm_grid, 256>>>(context, Wv, bv, Vb);

    size_t flash_smem = (size_t)FLASH_SMEM_FLOATS * sizeof(float);  // ~69 KB
    cudaFuncSetAttribute(flash_attn, cudaFuncAttributeMaxDynamicSharedMemorySize,
                         (int)flash_smem);
    flash_attn<<<dim3(QLEN / BQ, BATCH * NHEAD), 256, flash_smem>>>(Qb, Kb, Vb, Ab);

    sgemm_bias<<<gemm_grid, 256>>>(Ab, Wo, bo, (float*)d_out);
}